// round 8
// baseline (speedup 1.0000x reference)
#include <cuda_runtime.h>
#include <cuda_bf16.h>
#include <math.h>

#define BSZ   16
#define GR    52
#define HH    256
#define WW    256
#define HW    (HH * WW)
#define NT    1024
#define NW    (NT / 32)          // 32 warps
#define ITERS (HW / (NT * 4))    // 16 float4 iters per thread
#define GRP   4
#define NGRP  (ITERS / GRP)      // 4
#define MBYTES (HW * 2)          // 128 KB bf16 x matrix

__global__ __launch_bounds__(NT, 1)
void prm_kernel(const float* __restrict__ x,
                const float* __restrict__ wgt,
                const float* __restrict__ bias,
                const float* __restrict__ one,
                const float* __restrict__ zero,
                const float* __restrict__ theta,
                const float* __restrict__ scale,
                float* __restrict__ out)
{
    extern __shared__ __align__(16) char Mraw[];   // 128 KB bf16 x matrix
    __shared__ __align__(16) float glut[HH];       // row gaussian / folded G
    __shared__ __align__(16) float hlut[WW];       // col gaussian / folded H
    __shared__ float red[6][NW];
    __shared__ float rv[NW]; __shared__ int rix[NW];
    __shared__ float bc[8];

    const int p    = blockIdx.x;          // plane = b*GR + g
    const int g    = p % GR;
    const int tid  = threadIdx.x;
    const int lane = tid & 31;
    const int wid  = tid >> 5;

    const float4* x4 = (const float4*)x + (size_t)p * (HW / 4);
    float4*       o4 = (float4*)out     + (size_t)p * (HW / 4);

    const int rsub = tid >> 6;            // row offset within the 16-row stripe
    const int csub = tid & 63;            // col group

    // ================= Pass 1: the only DRAM read of x (lean) =================
    // iteration it: row = 16*it + rsub, cols 4*csub + {0..3}
    float bv = -3.402823466e38f;
    int   bi = 0x7fffffff;
    float s0 = 0.f, s1 = 0.f, q0a = 0.f, q1a = 0.f;

    #pragma unroll
    for (int grp = 0; grp < NGRP; ++grp) {
        float4 v[GRP];
        #pragma unroll
        for (int j = 0; j < GRP; ++j)
            v[j] = x4[(grp * GRP + j) * NT + tid];
        #pragma unroll
        for (int j = 0; j < GRP; ++j) {
            int it = grp * GRP + j;
            float4 t = v[j];
            int i0 = ((it * NT + tid) << 2);
            s0  += t.x + t.y;            s1  += t.z + t.w;
            q0a += t.x * t.x + t.y * t.y; q1a += t.z * t.z + t.w * t.w;
            // store x as bf16 into smem matrix
            __nv_bfloat162 p01 = __floats2bfloat162_rn(t.x, t.y);
            __nv_bfloat162 p23 = __floats2bfloat162_rn(t.z, t.w);
            uint2 pk = { *(unsigned*)&p01, *(unsigned*)&p23 };
            *(uint2*)(Mraw + 512 * (16 * it + rsub) + 8 * csub) = pk;
            // argmax (first occurrence)
            float m = fmaxf(fmaxf(t.x, t.y), fmaxf(t.z, t.w));
            if (m > bv) {
                bv = m;
                bi = i0 + (t.x == m ? 0 : (t.y == m ? 1 : (t.z == m ? 2 : 3)));
            }
        }
    }

    // block reduce sum / sumsq / argmax (once)
    float s = s0 + s1, s2 = q0a + q1a;
    #pragma unroll
    for (int o = 16; o; o >>= 1) {
        s  += __shfl_down_sync(0xffffffffu, s,  o);
        s2 += __shfl_down_sync(0xffffffffu, s2, o);
        float ov = __shfl_down_sync(0xffffffffu, bv, o);
        int   oi = __shfl_down_sync(0xffffffffu, bi, o);
        if (ov > bv || (ov == bv && oi < bi)) { bv = ov; bi = oi; }
    }
    if (lane == 0) { red[0][wid] = s; red[1][wid] = s2; rv[wid] = bv; rix[wid] = bi; }
    __syncthreads();

    if (wid == 0) {
        s  = red[0][lane]; s2 = red[1][lane];
        bv = rv[lane];     bi = rix[lane];
        #pragma unroll
        for (int o = 16; o; o >>= 1) {
            s  += __shfl_down_sync(0xffffffffu, s,  o);
            s2 += __shfl_down_sync(0xffffffffu, s2, o);
            float ov = __shfl_down_sync(0xffffffffu, bv, o);
            int   oi = __shfl_down_sync(0xffffffffu, bi, o);
            if (ov > bv || (ov == bv && oi < bi)) { bv = ov; bi = oi; }
        }
        if (lane == 0) {
            bc[0] = (float)(bi >> 8);                  // qrow
            bc[1] = (float)(bi & 255);                 // qcol
            bc[2] = bv * zero[g];                      // A
            bc[3] = s * (1.0f / (float)HW) * one[g];   // B
            bc[4] = s;                                 // Sx
            bc[5] = s2;                                // Sx2
        }
    }
    __syncthreads();

    // ================= Gaussian LUTs (raw, unscaled) ==========================
    {
        float sigma  = scale[0];
        float ln     = -logf(sigma) - 0.91893853320467274f;
        float inv2s2 = 0.5f / (sigma * sigma);
        if (tid < HH) {
            float d = fabsf((float)tid - bc[0]) * theta[0];
            glut[tid] = __expf(ln - d * d * inv2s2);
        } else if (tid < HH + WW) {
            int   c = tid - HH;
            float d = fabsf((float)c - bc[1]) * theta[1];
            hlut[c] = __expf(ln - d * d * inv2s2);
        }
    }
    __syncthreads();

    // ===== smem sweep: all LUT-weighted stats from the bf16 x matrix ==========
    // warp w handles rows [8w, 8w+8); lane reads 8 bf16 (cols 8*lane..+7)
    float t3 = 0.f, t4 = 0.f, t5 = 0.f, t6 = 0.f, t7 = 0.f, t12 = 0.f;
    {
        float4 ha  = *(const float4*)&hlut[8 * lane];
        float4 hb  = *(const float4*)&hlut[8 * lane + 4];
        float4 ha2 = { ha.x * ha.x, ha.y * ha.y, ha.z * ha.z, ha.w * ha.w };
        float4 hb2 = { hb.x * hb.x, hb.y * hb.y, hb.z * hb.z, hb.w * hb.w };
        #pragma unroll
        for (int r8 = 0; r8 < 8; ++r8) {
            int r = 8 * wid + r8;
            uint4 mm = *(const uint4*)(Mraw + 512 * r + 16 * lane);
            float2 a0 = __bfloat1622float2(*(__nv_bfloat162*)&mm.x);
            float2 a1 = __bfloat1622float2(*(__nv_bfloat162*)&mm.y);
            float2 a2 = __bfloat1622float2(*(__nv_bfloat162*)&mm.z);
            float2 a3 = __bfloat1622float2(*(__nv_bfloat162*)&mm.w);
            // squares
            float x0 = a0.x * a0.x, x1 = a0.y * a0.y;
            float x2 = a1.x * a1.x, x3 = a1.y * a1.y;
            float x4v = a2.x * a2.x, x5 = a2.y * a2.y;
            float x6 = a3.x * a3.x, x7 = a3.y * a3.y;
            float sx   = (a0.x + a0.y) + (a1.x + a1.y) + (a2.x + a2.y) + (a3.x + a3.y);
            float sxh  = a0.x * ha.x + a0.y * ha.y + a1.x * ha.z + a1.y * ha.w
                       + a2.x * hb.x + a2.y * hb.y + a3.x * hb.z + a3.y * hb.w;
            float sm   = (x0 + x1) + (x2 + x3) + (x4v + x5) + (x6 + x7);
            float smh  = x0 * ha.x + x1 * ha.y + x2 * ha.z + x3 * ha.w
                       + x4v * hb.x + x5 * hb.y + x6 * hb.z + x7 * hb.w;
            float smh2 = x0 * ha2.x + x1 * ha2.y + x2 * ha2.z + x3 * ha2.w
                       + x4v * hb2.x + x5 * hb2.y + x6 * hb2.z + x7 * hb2.w;
            float gr = glut[r];
            t3  += gr * sm;         // Σ x² g
            t4  += smh;             // Σ x² h
            t5  += gr * gr * sm;    // Σ x² g²
            t6  += smh2;            // Σ x² h²
            t7  += gr * smh;        // Σ x² g h
            t12 += gr * sx + sxh;   // Σ x (g + h)
        }
    }
    #pragma unroll
    for (int o = 16; o; o >>= 1) {
        t3  += __shfl_down_sync(0xffffffffu, t3,  o);
        t4  += __shfl_down_sync(0xffffffffu, t4,  o);
        t5  += __shfl_down_sync(0xffffffffu, t5,  o);
        t6  += __shfl_down_sync(0xffffffffu, t6,  o);
        t7  += __shfl_down_sync(0xffffffffu, t7,  o);
        t12 += __shfl_down_sync(0xffffffffu, t12, o);
    }
    if (lane == 0) {
        red[0][wid] = t3; red[1][wid] = t4; red[2][wid] = t5;
        red[3][wid] = t6; red[4][wid] = t7; red[5][wid] = t12;
    }
    __syncthreads();

    if (wid == 0) {
        t3  = red[0][lane]; t4 = red[1][lane]; t5 = red[2][lane];
        t6  = red[3][lane]; t7 = red[4][lane]; t12 = red[5][lane];
        #pragma unroll
        for (int o = 16; o; o >>= 1) {
            t3  += __shfl_down_sync(0xffffffffu, t3,  o);
            t4  += __shfl_down_sync(0xffffffffu, t4,  o);
            t5  += __shfl_down_sync(0xffffffffu, t5,  o);
            t6  += __shfl_down_sync(0xffffffffu, t6,  o);
            t7  += __shfl_down_sync(0xffffffffu, t7,  o);
            t12 += __shfl_down_sync(0xffffffffu, t12, o);
        }
        if (lane == 0) {
            float A = bc[2], B = bc[3], Sx = bc[4], Sx2 = bc[5];
            float sxe   = 0.5f  * A * t12;
            float sx2e  = 0.5f  * A * (t3 + t4);
            float sx2e2 = 0.25f * A * A * (t5 + t6 + 2.f * t7);
            float Ssim  = sxe + B * Sx;
            float Ssim2 = sx2e2 + 2.f * B * sx2e + B * B * Sx2;
            float mean  = Ssim * (1.0f / (float)HW);
            float var   = (Ssim2 - Ssim * Ssim * (1.0f / (float)HW)) * (1.0f / (float)(HW - 1));
            float sd    = sqrtf(fmaxf(var, 0.f)) + 1e-5f;
            float k1    = wgt[g] / sd;
            bc[0] = 0.5f * A * k1;          // LUT scale
            bc[1] = B * k1;                 // folded into G
            bc[2] = bias[g] - mean * k1;    // c0
        }
    }
    __syncthreads();

    // fold constants into LUTs: G = 0.5*A*k1*g + B*k1 ; H = 0.5*A*k1*h
    {
        float sA = bc[0], Bk = bc[1];
        if (tid < HH)               glut[tid] = fmaf(glut[tid], sA, Bk);
        else if (tid < HH + WW)     hlut[tid - HH] *= sA;
    }
    __syncthreads();

    // ================= Pass 2: gated output (x re-read hits L2) ===============
    {
        float c0 = bc[2];
        float4 Hc = *(const float4*)&hlut[4 * csub];   // cols fixed per thread
        #pragma unroll
        for (int grp = 0; grp < NGRP; ++grp) {
            float4 v[GRP];
            float  gr[GRP];
            #pragma unroll
            for (int j = 0; j < GRP; ++j) {
                int it = grp * GRP + j;
                v[j]  = x4[it * NT + tid];
                gr[j] = glut[16 * it + rsub];
            }
            #pragma unroll
            for (int j = 0; j < GRP; ++j) {
                float4 t = v[j];
                float t0  = fmaf(t.x, gr[j] + Hc.x, c0);
                float t1  = fmaf(t.y, gr[j] + Hc.y, c0);
                float t2  = fmaf(t.z, gr[j] + Hc.z, c0);
                float t3v = fmaf(t.w, gr[j] + Hc.w, c0);
                float4 o;
                o.x = __fdividef(t.x, 1.f + __expf(-t0));
                o.y = __fdividef(t.y, 1.f + __expf(-t1));
                o.z = __fdividef(t.z, 1.f + __expf(-t2));
                o.w = __fdividef(t.w, 1.f + __expf(-t3v));
                __stcs(&o4[(grp * GRP + j) * NT + tid], o);  // stream the output
            }
        }
    }
}

extern "C" void kernel_launch(void* const* d_in, const int* in_sizes, int n_in,
                              void* d_out, int out_size)
{
    const float* x     = (const float*)d_in[0];
    const float* wgt   = (const float*)d_in[1];
    const float* bias  = (const float*)d_in[2];
    const float* one   = (const float*)d_in[3];
    const float* zero  = (const float*)d_in[4];
    const float* theta = (const float*)d_in[5];
    const float* scale = (const float*)d_in[6];
    float* out = (float*)d_out;

    cudaFuncSetAttribute(prm_kernel, cudaFuncAttributeMaxDynamicSharedMemorySize, MBYTES);
    prm_kernel<<<BSZ * GR, NT, MBYTES>>>(x, wgt, bias, one, zero, theta, scale, out);
}

// round 9
// speedup vs baseline: 1.1914x; 1.1914x over previous
#include <cuda_runtime.h>
#include <math.h>

#define BSZ   16
#define GR    52
#define HH    256
#define WW    256
#define HW    (HH * WW)
#define NT    1024
#define NW    (NT / 32)           // 32 warps
#define HALF4 (HW / 8)            // 8192 float4 per half-plane
#define ITERS (HALF4 / NT)        // 8 float4 iters per thread
#define GRPSZ 4
#define NGRP  (ITERS / GRPSZ)     // 2
#define MBYTES (HW / 2 * 4)       // 131072 B fp32 half-plane

#define CLUSTER_SYNC_() do { \
    asm volatile("barrier.cluster.arrive.aligned;" ::: "memory"); \
    asm volatile("barrier.cluster.wait.aligned;" ::: "memory"); } while (0)

__device__ __forceinline__ float ld_peer_f32(unsigned saddr, unsigned peer) {
    unsigned ra; float v;
    asm("mapa.shared::cluster.u32 %0, %1, %2;" : "=r"(ra) : "r"(saddr), "r"(peer));
    asm volatile("ld.shared::cluster.f32 %0, [%1];" : "=f"(v) : "r"(ra));
    return v;
}

__global__ __launch_bounds__(NT, 1) __cluster_dims__(2, 1, 1)
void prm_kernel(const float* __restrict__ x,
                const float* __restrict__ wgt,
                const float* __restrict__ bias,
                const float* __restrict__ one,
                const float* __restrict__ zero,
                const float* __restrict__ theta,
                const float* __restrict__ scale,
                float* __restrict__ out)
{
    extern __shared__ __align__(16) float xs[];    // fp32 half-plane [128][256]
    __shared__ __align__(16) float glut[HH / 2];   // own 128 rows (raw, then folded)
    __shared__ __align__(16) float hlut[WW];       // all 256 cols
    __shared__ float red[6][NW];
    __shared__ float rv[NW]; __shared__ int rix[NW];
    __shared__ __align__(16) float xchA[4];        // s, s2, bv, bi(bits)
    __shared__ __align__(16) float xchB[6];        // sweep partials
    __shared__ float bc[8];

    const int      plane = blockIdx.x >> 1;        // plane = b*GR + g
    const unsigned rank  = blockIdx.x & 1;         // which half (rows 128*rank..)
    const unsigned peer  = rank ^ 1;
    const int      g     = plane % GR;
    const int tid  = threadIdx.x;
    const int lane = tid & 31;
    const int wid  = tid >> 5;
    const int rsub = tid >> 6;                     // row offset within 16-row stripe
    const int csub = tid & 63;                     // col group

    const float4* x4 = (const float4*)x + (size_t)plane * (HW / 4) + (size_t)rank * HALF4;
    float4*       o4 = (float4*)out     + (size_t)plane * (HW / 4) + (size_t)rank * HALF4;
    float4*       xs4 = (float4*)xs;

    // ================= Pass 1: only DRAM read; x -> fp32 smem ================
    float bv = -3.402823466e38f;
    int   bi = 0x7fffffff;                         // GLOBAL linear index in plane
    float s0 = 0.f, s1 = 0.f, q0a = 0.f, q1a = 0.f;

    #pragma unroll
    for (int grp = 0; grp < NGRP; ++grp) {
        float4 v[GRPSZ];
        #pragma unroll
        for (int j = 0; j < GRPSZ; ++j)
            v[j] = x4[(grp * GRPSZ + j) * NT + tid];
        #pragma unroll
        for (int j = 0; j < GRPSZ; ++j) {
            int idx4 = (grp * GRPSZ + j) * NT + tid;
            float4 t = v[j];
            xs4[idx4] = t;                         // keep fp32 copy in smem
            int i0 = (int)(rank << 15) + (idx4 << 2);
            s0  += t.x + t.y;             s1  += t.z + t.w;
            q0a += t.x * t.x + t.y * t.y; q1a += t.z * t.z + t.w * t.w;
            float m = fmaxf(fmaxf(t.x, t.y), fmaxf(t.z, t.w));
            if (m > bv) {                          // first occurrence
                bv = m;
                bi = i0 + (t.x == m ? 0 : (t.y == m ? 1 : (t.z == m ? 2 : 3)));
            }
        }
    }

    // block reduce s/s2/argmax
    float s = s0 + s1, s2 = q0a + q1a;
    #pragma unroll
    for (int o = 16; o; o >>= 1) {
        s  += __shfl_down_sync(0xffffffffu, s,  o);
        s2 += __shfl_down_sync(0xffffffffu, s2, o);
        float ov = __shfl_down_sync(0xffffffffu, bv, o);
        int   oi = __shfl_down_sync(0xffffffffu, bi, o);
        if (ov > bv || (ov == bv && oi < bi)) { bv = ov; bi = oi; }
    }
    if (lane == 0) { red[0][wid] = s; red[1][wid] = s2; rv[wid] = bv; rix[wid] = bi; }
    __syncthreads();
    if (wid == 0) {
        s  = red[0][lane]; s2 = red[1][lane];
        bv = rv[lane];     bi = rix[lane];
        #pragma unroll
        for (int o = 16; o; o >>= 1) {
            s  += __shfl_down_sync(0xffffffffu, s,  o);
            s2 += __shfl_down_sync(0xffffffffu, s2, o);
            float ov = __shfl_down_sync(0xffffffffu, bv, o);
            int   oi = __shfl_down_sync(0xffffffffu, bi, o);
            if (ov > bv || (ov == bv && oi < bi)) { bv = ov; bi = oi; }
        }
        if (lane == 0) {
            xchA[0] = s; xchA[1] = s2; xchA[2] = bv; xchA[3] = __int_as_float(bi);
        }
    }
    __syncthreads();
    CLUSTER_SYNC_();                               // publish xchA cluster-wide

    // -------- combine half-plane partials (both CTAs compute identically) -----
    if (tid == 0) {
        unsigned a0 = (unsigned)__cvta_generic_to_shared(&xchA[0]);
        float ps  = ld_peer_f32(a0,      peer);
        float ps2 = ld_peer_f32(a0 + 4,  peer);
        float pbv = ld_peer_f32(a0 + 8,  peer);
        int   pbi = __float_as_int(ld_peer_f32(a0 + 12, peer));
        float os = xchA[0], os2 = xchA[1], obv = xchA[2];
        int   obi = __float_as_int(xchA[3]);
        float Sx = os + ps, Sx2 = os2 + ps2;
        float gbv = obv; int gbi = obi;
        if (pbv > gbv || (pbv == gbv && pbi < gbi)) { gbv = pbv; gbi = pbi; }
        bc[0] = (float)(gbi >> 8);                 // qrow (global)
        bc[1] = (float)(gbi & 255);                // qcol
        bc[2] = gbv * zero[g];                     // A
        bc[3] = Sx * (1.0f / (float)HW) * one[g];  // B
        bc[4] = Sx;
        bc[5] = Sx2;
    }
    __syncthreads();

    // ================= Gaussian LUTs (raw) ====================================
    {
        float sigma  = scale[0];
        float ln     = -logf(sigma) - 0.91893853320467274f;
        float inv2s2 = 0.5f / (sigma * sigma);
        if (tid < HH / 2) {                        // own global rows
            float r = (float)(tid + 128 * (int)rank);
            float d = fabsf(r - bc[0]) * theta[0];
            glut[tid] = __expf(ln - d * d * inv2s2);
        } else if (tid < HH / 2 + WW) {
            int   c = tid - HH / 2;
            float d = fabsf((float)c - bc[1]) * theta[1];
            hlut[c] = __expf(ln - d * d * inv2s2);
        }
    }
    __syncthreads();

    // ===== smem sweep over own fp32 half: 6 LUT-weighted stats ===============
    // warp w: local rows [4w, 4w+4); lane covers cols [8*lane, 8*lane+8)
    float t3 = 0.f, t4 = 0.f, t5 = 0.f, t6 = 0.f, t7 = 0.f, t12 = 0.f;
    {
        float4 ha  = *(const float4*)&hlut[8 * lane];
        float4 hb  = *(const float4*)&hlut[8 * lane + 4];
        float4 ha2 = { ha.x * ha.x, ha.y * ha.y, ha.z * ha.z, ha.w * ha.w };
        float4 hb2 = { hb.x * hb.x, hb.y * hb.y, hb.z * hb.z, hb.w * hb.w };
        #pragma unroll
        for (int r4 = 0; r4 < 4; ++r4) {
            int r = 4 * wid + r4;
            const float4* rowp = (const float4*)&xs[256 * r + 8 * lane];
            float4 u = rowp[0], w4 = rowp[1];
            float x0 = u.x * u.x,  x1 = u.y * u.y,  x2 = u.z * u.z,  x3 = u.w * u.w;
            float x4v = w4.x * w4.x, x5 = w4.y * w4.y, x6 = w4.z * w4.z, x7 = w4.w * w4.w;
            float sx   = (u.x + u.y) + (u.z + u.w) + (w4.x + w4.y) + (w4.z + w4.w);
            float sxh  = u.x * ha.x + u.y * ha.y + u.z * ha.z + u.w * ha.w
                       + w4.x * hb.x + w4.y * hb.y + w4.z * hb.z + w4.w * hb.w;
            float sm   = (x0 + x1) + (x2 + x3) + (x4v + x5) + (x6 + x7);
            float smh  = x0 * ha.x + x1 * ha.y + x2 * ha.z + x3 * ha.w
                       + x4v * hb.x + x5 * hb.y + x6 * hb.z + x7 * hb.w;
            float smh2 = x0 * ha2.x + x1 * ha2.y + x2 * ha2.z + x3 * ha2.w
                       + x4v * hb2.x + x5 * hb2.y + x6 * hb2.z + x7 * hb2.w;
            float gr = glut[r];
            t3  += gr * sm;
            t4  += smh;
            t5  += gr * gr * sm;
            t6  += smh2;
            t7  += gr * smh;
            t12 += gr * sx + sxh;
        }
    }
    #pragma unroll
    for (int o = 16; o; o >>= 1) {
        t3  += __shfl_down_sync(0xffffffffu, t3,  o);
        t4  += __shfl_down_sync(0xffffffffu, t4,  o);
        t5  += __shfl_down_sync(0xffffffffu, t5,  o);
        t6  += __shfl_down_sync(0xffffffffu, t6,  o);
        t7  += __shfl_down_sync(0xffffffffu, t7,  o);
        t12 += __shfl_down_sync(0xffffffffu, t12, o);
    }
    if (lane == 0) {
        red[0][wid] = t3; red[1][wid] = t4; red[2][wid] = t5;
        red[3][wid] = t6; red[4][wid] = t7; red[5][wid] = t12;
    }
    __syncthreads();
    if (wid == 0) {
        t3  = red[0][lane]; t4 = red[1][lane]; t5 = red[2][lane];
        t6  = red[3][lane]; t7 = red[4][lane]; t12 = red[5][lane];
        #pragma unroll
        for (int o = 16; o; o >>= 1) {
            t3  += __shfl_down_sync(0xffffffffu, t3,  o);
            t4  += __shfl_down_sync(0xffffffffu, t4,  o);
            t5  += __shfl_down_sync(0xffffffffu, t5,  o);
            t6  += __shfl_down_sync(0xffffffffu, t6,  o);
            t7  += __shfl_down_sync(0xffffffffu, t7,  o);
            t12 += __shfl_down_sync(0xffffffffu, t12, o);
        }
        if (lane == 0) {
            xchB[0] = t3; xchB[1] = t4; xchB[2] = t5;
            xchB[3] = t6; xchB[4] = t7; xchB[5] = t12;
        }
    }
    __syncthreads();
    CLUSTER_SYNC_();                               // publish xchB cluster-wide

    if (tid == 0) {
        unsigned b0 = (unsigned)__cvta_generic_to_shared(&xchB[0]);
        float T3 = xchB[0] + ld_peer_f32(b0,      peer);
        float T4 = xchB[1] + ld_peer_f32(b0 + 4,  peer);
        float T5 = xchB[2] + ld_peer_f32(b0 + 8,  peer);
        float T6 = xchB[3] + ld_peer_f32(b0 + 12, peer);
        float T7 = xchB[4] + ld_peer_f32(b0 + 16, peer);
        float T12 = xchB[5] + ld_peer_f32(b0 + 20, peer);
        float A = bc[2], B = bc[3], Sx = bc[4], Sx2 = bc[5];
        float sxe   = 0.5f  * A * T12;
        float sx2e  = 0.5f  * A * (T3 + T4);
        float sx2e2 = 0.25f * A * A * (T5 + T6 + 2.f * T7);
        float Ssim  = sxe + B * Sx;
        float Ssim2 = sx2e2 + 2.f * B * sx2e + B * B * Sx2;
        float mean  = Ssim * (1.0f / (float)HW);
        float var   = (Ssim2 - Ssim * Ssim * (1.0f / (float)HW)) * (1.0f / (float)(HW - 1));
        float sd    = sqrtf(fmaxf(var, 0.f)) + 1e-5f;
        float k1    = wgt[g] / sd;
        bc[0] = 0.5f * A * k1;                     // LUT scale
        bc[1] = B * k1;                            // folded into G
        bc[2] = bias[g] - mean * k1;               // c0
    }
    __syncthreads();
    CLUSTER_SYNC_();   // peer finished reading my xchA/xchB -> safe to exit later

    // fold constants into LUTs: G = 0.5*A*k1*g + B*k1 ; H = 0.5*A*k1*h
    {
        float sA = bc[0], Bk = bc[1];
        if (tid < HH / 2)                glut[tid] = fmaf(glut[tid], sA, Bk);
        else if (tid < HH / 2 + WW)      hlut[tid - HH / 2] *= sA;
    }
    __syncthreads();

    // ================= Pass 2: gated output, x read from smem ================
    {
        float c0 = bc[2];
        float4 Hc = *(const float4*)&hlut[4 * csub];   // cols fixed per thread
        #pragma unroll
        for (int it = 0; it < ITERS; ++it) {
            int idx4 = it * NT + tid;
            float4 t = xs4[idx4];
            float gr = glut[16 * it + rsub];           // local row
            float t0  = fmaf(t.x, gr + Hc.x, c0);
            float t1  = fmaf(t.y, gr + Hc.y, c0);
            float t2  = fmaf(t.z, gr + Hc.z, c0);
            float t3v = fmaf(t.w, gr + Hc.w, c0);
            float4 o;
            o.x = __fdividef(t.x, 1.f + __expf(-t0));
            o.y = __fdividef(t.y, 1.f + __expf(-t1));
            o.z = __fdividef(t.z, 1.f + __expf(-t2));
            o.w = __fdividef(t.w, 1.f + __expf(-t3v));
            __stcs(&o4[idx4], o);
        }
    }
}

extern "C" void kernel_launch(void* const* d_in, const int* in_sizes, int n_in,
                              void* d_out, int out_size)
{
    const float* x     = (const float*)d_in[0];
    const float* wgt   = (const float*)d_in[1];
    const float* bias  = (const float*)d_in[2];
    const float* one   = (const float*)d_in[3];
    const float* zero  = (const float*)d_in[4];
    const float* theta = (const float*)d_in[5];
    const float* scale = (const float*)d_in[6];
    float* out = (float*)d_out;

    cudaFuncSetAttribute(prm_kernel, cudaFuncAttributeMaxDynamicSharedMemorySize, MBYTES);
    prm_kernel<<<BSZ * GR * 2, NT, MBYTES>>>(x, wgt, bias, one, zero, theta, scale, out);
}